// round 15
// baseline (speedup 1.0000x reference)
#include <cuda_runtime.h>

// Fixed shapes for CIFAR10Net_86096914416128
#define TT    16
#define NB    32
#define CIN   3
#define HH    32
#define WWID  32
#define COUT  128
#define KW27  27

// x tile (u64 units): per t, 15 pair-rows (cin*5 + j) x 34 logical cols
#define PROWS   5
#define NROWS   (CIN * PROWS)        // 15
#define RSTRIDE 38                   // 34 + 2x2 gaps -> 304B rows, 16B aligned
#define TSTRIDE (NROWS * RSTRIDE)    // 570 u64 per t
#define TCHUNK  8
#define NPAIRS_T (NROWS * 34)        // 510 pairs per t
#define NTHR    128                  // small CTA: 4 per SM, de-synced barriers

typedef unsigned long long u64;

__device__ float g_w[COUT * KW27];

// ---------- packed f32x2 helpers ----------
__device__ __forceinline__ u64 pack2(float a, float b) {
    u64 r; asm("mov.b64 %0,{%1,%2};" : "=l"(r) : "f"(a), "f"(b)); return r;
}
__device__ __forceinline__ void unpack2(u64 v, float& a, float& b) {
    asm("mov.b64 {%0,%1},%2;" : "=f"(a), "=f"(b) : "l"(v));
}
__device__ __forceinline__ u64 ffma2(u64 a, u64 b, u64 c) {
    asm("fma.rn.f32x2 %0,%1,%2,%0;" : "+l"(c) : "l"(a), "l"(b)); return c;
}
__device__ __forceinline__ u64 fadd2(u64 a, u64 b) {
    u64 r; asm("add.rn.f32x2 %0,%1,%2;" : "=l"(r) : "l"(a), "l"(b)); return r;
}
__device__ __forceinline__ u64 fmul2(u64 a, u64 b) {
    u64 r; asm("mul.rn.f32x2 %0,%1,%2;" : "=l"(r) : "l"(a), "l"(b)); return r;
}

// conflict-free column map: 16B gap every 16 cols
__device__ __forceinline__ int colmap(int c) { return c + 2 * (c >> 4); }

// ---------- weight prep: clip + fp32 weight-standardization (matches ref) ----------
__global__ void prep_kernel(const float* __restrict__ w,
                            const float* __restrict__ nw,
                            const float* __restrict__ nb) {
    int c = threadIdx.x;
    if (c >= COUT) return;
    float v[KW27];
    float s = 0.0f;
#pragma unroll
    for (int i = 0; i < KW27; i++) {
        float t = w[c * KW27 + i];
        t = fminf(4.0f, fmaxf(-4.0f, t));
        v[i] = t;
        s = __fadd_rn(s, t);
    }
    float mean = __fdiv_rn(s, 27.0f);
    float ss = 0.0f;
#pragma unroll
    for (int i = 0; i < KW27; i++) {
        float d = __fsub_rn(v[i], mean);
        ss = __fadd_rn(ss, __fmul_rn(d, d));
    }
    float var   = __fdiv_rn(ss, 26.0f);
    float denom = __fsqrt_rn(__fadd_rn(var, 1e-5f));
    float nwc = nw[c];
    float nbc = nb[c];
#pragma unroll
    for (int i = 0; i < KW27; i++) {
        float std = __fdiv_rn(__fsub_rn(v[i], mean), denom);
        g_w[c * KW27 + i] = __fadd_rn(__fmul_rn(std, nwc), nbc);
    }
}

// ---------- fused conv3x3 + LIF scan; 4 rows/thread, 128-thread CTAs ----------
// Grid: 2048 = b(32) * cgroup(8, 16ch) * rowquad(8). Block: 128 = ch(16)*seg(8).
// Thread: 1 channel, 4 rows (two f32x2 pair-accs P,Q), 4 cols = 16 outputs.
// 4 CTAs/SM -> 4 independent barrier groups; staging of one CTA overlaps
// compute of the other three.
__global__ void __launch_bounds__(NTHR, 4)
snn_kernel(const float* __restrict__ x,
           const float* __restrict__ thr,
           float* __restrict__ out) {
    __shared__ __align__(16) u64 xs[TCHUNK * TSTRIDE];   // 36480 B

    const int tid = threadIdx.x;
    const int bid = blockIdx.x;
    const int bb  = bid >> 6;          // batch
    const int cg  = (bid >> 3) & 7;    // 16-channel group
    const int rq  = bid & 7;           // row quad
    const int r0  = rq * 4;

    const int cl  = tid >> 3;          // channel in group (0..15)
    const int seg = tid & 7;
    const int w0  = seg * 4;
    const int c   = cg * 16 + cl;

    // 27 weights duplicated into both f32x2 lanes (registers)
    u64 wp[KW27];
#pragma unroll
    for (int i = 0; i < KW27; i++) {
        float wv = g_w[c * KW27 + i];
        wp[i] = pack2(wv, wv);
    }
    const float th = thr[c];
    const float CSG = 1.0f - (float)(1.0 / 3.5);
    const u64 C2 = pack2(CSG, CSG);

    const int HW = HH * WWID;

    // LIF state: P = rows (r0, r0+1), Q = rows (r0+2, r0+3); 4 cols each
    u64 uP[4]  = {0,0,0,0}, sgP[4] = {0,0,0,0};
    u64 uQ[4]  = {0,0,0,0}, sgQ[4] = {0,0,0,0};

    const int oo0 = colmap(w0);
    const int oo1 = colmap(w0 + 2);
    const int oo2 = colmap(w0 + 4);

    float* ob = out + ((size_t)bb * COUT + c) * HW + (size_t)r0 * WWID + w0;
    const size_t ostride = (size_t)NB * COUT * HW;

    for (int h = 0; h < TT / TCHUNK; h++) {
        __syncthreads();   // previous phase readers done
        // ---- stage TCHUNK timesteps: pair-row j covers rows (r0-1+j, r0+j) ----
        for (int idx = tid; idx < TCHUNK * NPAIRS_T; idx += NTHR) {
            int t   = idx / NPAIRS_T;
            int rem = idx - t * NPAIRS_T;
            int row = rem / 34;            // cin*5 + j
            int col = rem - row * 34;
            int cin = row / PROWS;
            int j   = row - cin * PROWS;
            int gw  = col - 1;
            float va = 0.0f, vb = 0.0f;
            if (gw >= 0 && gw < WWID) {
                int ra = r0 - 1 + j;       // [-1, 31]
                int rb = r0 + j;           // [0, 32]
                const float* p = x + ((size_t)((h * TCHUNK + t) * NB + bb) * CIN + cin) * HW + gw;
                if (ra >= 0 && ra < HH) va = p[ra * WWID];
                if (rb < HH)            vb = p[rb * WWID];
            }
            xs[t * TSTRIDE + row * RSTRIDE + colmap(col)] = pack2(va, vb);
        }
        __syncthreads();

#pragma unroll 1
        for (int t = 0; t < TCHUNK; t++) {
            const u64* tb = xs + t * TSTRIDE;

            u64 accP[4] = {0,0,0,0};
            u64 accQ[4] = {0,0,0,0};
#pragma unroll
            for (int cin = 0; cin < 3; cin++) {
#pragma unroll
                for (int j = 0; j < PROWS; j++) {
                    const u64* rowp = tb + (cin * PROWS + j) * RSTRIDE;
                    ulonglong2 p0 = *reinterpret_cast<const ulonglong2*>(rowp + oo0);
                    ulonglong2 p1 = *reinterpret_cast<const ulonglong2*>(rowp + oo1);
                    ulonglong2 p2 = *reinterpret_cast<const ulonglong2*>(rowp + oo2);
                    u64 xr[6] = {p0.x, p0.y, p1.x, p1.y, p2.x, p2.y};
                    if (j < 3) {                 // P: kh = j
                        const int wb = (cin * 3 + j) * 3;
#pragma unroll
                        for (int kw = 0; kw < 3; kw++) {
                            const u64 wv = wp[wb + kw];
#pragma unroll
                            for (int ww = 0; ww < 4; ww++)
                                accP[ww] = ffma2(wv, xr[ww + kw], accP[ww]);
                        }
                    }
                    if (j >= 2) {                // Q: kh = j - 2
                        const int wb = (cin * 3 + (j - 2)) * 3;
#pragma unroll
                        for (int kw = 0; kw < 3; kw++) {
                            const u64 wv = wp[wb + kw];
#pragma unroll
                            for (int ww = 0; ww < 4; ww++)
                                accQ[ww] = ffma2(wv, xr[ww + kw], accQ[ww]);
                        }
                    }
                }
            }

            // LIF update + spike/reset for both pair sets
            float p0v[4], p1v[4], q0v[4], q1v[4];
#pragma unroll
            for (int k = 0; k < 4; k++) {
                u64 s  = fmul2(fadd2(sgP[k], accP[k]), C2);   // sg=(sg+I)*(1-tg)
                u64 uu = fadd2(uP[k], s);                     // u = u_last + sg
                float ux, uy, sx, sy;
                unpack2(uu, ux, uy);
                unpack2(s,  sx, sy);
                p0v[k] = (ux >= th) ? 1.0f : 0.0f;
                p1v[k] = (uy >= th) ? 1.0f : 0.0f;
                if (ux >= th) { ux = 0.0f; sx = 0.0f; }
                if (uy >= th) { uy = 0.0f; sy = 0.0f; }
                uP[k]  = pack2(ux, uy);
                sgP[k] = pack2(sx, sy);

                s  = fmul2(fadd2(sgQ[k], accQ[k]), C2);
                uu = fadd2(uQ[k], s);
                unpack2(uu, ux, uy);
                unpack2(s,  sx, sy);
                q0v[k] = (ux >= th) ? 1.0f : 0.0f;
                q1v[k] = (uy >= th) ? 1.0f : 0.0f;
                if (ux >= th) { ux = 0.0f; sx = 0.0f; }
                if (uy >= th) { uy = 0.0f; sy = 0.0f; }
                uQ[k]  = pack2(ux, uy);
                sgQ[k] = pack2(sx, sy);
            }
            float* op = ob + (size_t)(h * TCHUNK + t) * ostride;
            *reinterpret_cast<float4*>(op)            = make_float4(p0v[0], p0v[1], p0v[2], p0v[3]);
            *reinterpret_cast<float4*>(op + WWID)     = make_float4(p1v[0], p1v[1], p1v[2], p1v[3]);
            *reinterpret_cast<float4*>(op + 2 * WWID) = make_float4(q0v[0], q0v[1], q0v[2], q0v[3]);
            *reinterpret_cast<float4*>(op + 3 * WWID) = make_float4(q1v[0], q1v[1], q1v[2], q1v[3]);
        }
    }
}

extern "C" void kernel_launch(void* const* d_in, const int* in_sizes, int n_in,
                              void* d_out, int out_size) {
    const float* x  = (const float*)d_in[0];   // [16,32,3,32,32]
    const float* w  = (const float*)d_in[1];   // [128,3,3,3]
    const float* nw = (const float*)d_in[2];   // [128]
    const float* nb = (const float*)d_in[3];   // [128]
    const float* th = (const float*)d_in[4];   // [128]
    float* out = (float*)d_out;                // [16,32,128,32,32]

    prep_kernel<<<1, 128>>>(w, nw, nb);
    snn_kernel<<<2048, NTHR>>>(x, th, out);
}

// round 16
// speedup vs baseline: 1.1793x; 1.1793x over previous
#include <cuda_runtime.h>

// Fixed shapes for CIFAR10Net_86096914416128
#define TT    16
#define NB    32
#define CIN   3
#define HH    32
#define WWID  32
#define COUT  128
#define KW27  27

// x tile (u64 units): per t, 15 pair-rows (cin*5 + j) x 34 logical cols
#define PROWS   5
#define NROWS   (CIN * PROWS)        // 15
#define RSTRIDE 38                   // 34 + 2x2 gaps -> 304B rows, 16B aligned
#define TSTRIDE (NROWS * RSTRIDE)    // 570 u64 per t
#define NPAIRS_T (NROWS * 34)        // 510 pairs per t
#define SMEM_BYTES (TT * TSTRIDE * 8)   // 72960 B dynamic

typedef unsigned long long u64;

__device__ float g_w[COUT * KW27];

// ---------- packed f32x2 helpers ----------
__device__ __forceinline__ u64 pack2(float a, float b) {
    u64 r; asm("mov.b64 %0,{%1,%2};" : "=l"(r) : "f"(a), "f"(b)); return r;
}
__device__ __forceinline__ void unpack2(u64 v, float& a, float& b) {
    asm("mov.b64 {%0,%1},%2;" : "=f"(a), "=f"(b) : "l"(v));
}
__device__ __forceinline__ u64 ffma2(u64 a, u64 b, u64 c) {
    asm("fma.rn.f32x2 %0,%1,%2,%0;" : "+l"(c) : "l"(a), "l"(b)); return c;
}
__device__ __forceinline__ u64 fadd2(u64 a, u64 b) {
    u64 r; asm("add.rn.f32x2 %0,%1,%2;" : "=l"(r) : "l"(a), "l"(b)); return r;
}
__device__ __forceinline__ u64 fmul2(u64 a, u64 b) {
    u64 r; asm("mul.rn.f32x2 %0,%1,%2;" : "=l"(r) : "l"(a), "l"(b)); return r;
}

// conflict-free column map: 16B gap every 16 cols
__device__ __forceinline__ int colmap(int c) { return c + 2 * (c >> 4); }

// ---------- weight prep: clip + fp32 weight-standardization (matches ref) ----------
__global__ void prep_kernel(const float* __restrict__ w,
                            const float* __restrict__ nw,
                            const float* __restrict__ nb) {
    int c = threadIdx.x;
    if (c >= COUT) return;
    float v[KW27];
    float s = 0.0f;
#pragma unroll
    for (int i = 0; i < KW27; i++) {
        float t = w[c * KW27 + i];
        t = fminf(4.0f, fmaxf(-4.0f, t));
        v[i] = t;
        s = __fadd_rn(s, t);
    }
    float mean = __fdiv_rn(s, 27.0f);
    float ss = 0.0f;
#pragma unroll
    for (int i = 0; i < KW27; i++) {
        float d = __fsub_rn(v[i], mean);
        ss = __fadd_rn(ss, __fmul_rn(d, d));
    }
    float var   = __fdiv_rn(ss, 26.0f);
    float denom = __fsqrt_rn(__fadd_rn(var, 1e-5f));
    float nwc = nw[c];
    float nbc = nb[c];
#pragma unroll
    for (int i = 0; i < KW27; i++) {
        float std = __fdiv_rn(__fsub_rn(v[i], mean), denom);
        g_w[c * KW27 + i] = __fadd_rn(__fmul_rn(std, nwc), nbc);
    }
}

// ---------- fused conv3x3 + LIF scan; 4 rows/thread, all-t staged once ----------
// Grid: 1024 = b(32) * cgroup(4, 32ch) * rowquad(8). Block: 256 = ch(32)*seg(8).
// Thread: 1 channel, 4 rows (two f32x2 pair-accs P,Q), 4 cols = 16 outputs.
// Single staging phase + single barrier; compute runs barrier-free.
__global__ void __launch_bounds__(256, 2)
snn_kernel(const float* __restrict__ x,
           const float* __restrict__ thr,
           float* __restrict__ out) {
    extern __shared__ __align__(16) u64 xs[];   // TT * TSTRIDE u64 = 72960 B

    const int tid = threadIdx.x;
    const int bid = blockIdx.x;
    const int bb  = bid >> 5;          // batch
    const int cg  = (bid >> 3) & 3;    // 32-channel group
    const int rq  = bid & 7;           // row quad
    const int r0  = rq * 4;

    const int cl  = tid >> 3;          // channel in group
    const int seg = tid & 7;
    const int w0  = seg * 4;
    const int c   = cg * 32 + cl;

    // ---- stage ALL 16 timesteps (one phase, high MLP) ----
    for (int idx = tid; idx < TT * NPAIRS_T; idx += 256) {
        int t   = idx / NPAIRS_T;
        int rem = idx - t * NPAIRS_T;
        int row = rem / 34;            // cin*5 + j
        int col = rem - row * 34;
        int cin = row / PROWS;
        int j   = row - cin * PROWS;
        int gw  = col - 1;
        float va = 0.0f, vb = 0.0f;
        if (gw >= 0 && gw < WWID) {
            int ra = r0 - 1 + j;       // [-1, 31]
            int rb = r0 + j;           // [0, 32]
            const float* p = x + ((size_t)(t * NB + bb) * CIN + cin) * (HH * WWID) + gw;
            if (ra >= 0 && ra < HH) va = p[ra * WWID];
            if (rb < HH)            vb = p[rb * WWID];
        }
        xs[t * TSTRIDE + row * RSTRIDE + colmap(col)] = pack2(va, vb);
    }

    // 27 weights duplicated into both f32x2 lanes (registers); overlaps staging LDGs
    u64 wp[KW27];
#pragma unroll
    for (int i = 0; i < KW27; i++) {
        float wv = g_w[c * KW27 + i];
        wp[i] = pack2(wv, wv);
    }
    const float th = thr[c];
    const float CSG = 1.0f - (float)(1.0 / 3.5);
    const u64 C2 = pack2(CSG, CSG);

    const int HW = HH * WWID;

    // LIF state: P = rows (r0, r0+1), Q = rows (r0+2, r0+3); 4 cols each
    u64 uP[4]  = {0,0,0,0}, sgP[4] = {0,0,0,0};
    u64 uQ[4]  = {0,0,0,0}, sgQ[4] = {0,0,0,0};

    const int oo0 = colmap(w0);
    const int oo1 = colmap(w0 + 2);
    const int oo2 = colmap(w0 + 4);

    float* ob = out + ((size_t)bb * COUT + c) * HW + (size_t)r0 * WWID + w0;
    const size_t ostride = (size_t)NB * COUT * HW;

    __syncthreads();   // the only barrier

#pragma unroll 1
    for (int t = 0; t < TT; t++) {
        const u64* tb = xs + t * TSTRIDE;

        u64 accP[4] = {0,0,0,0};
        u64 accQ[4] = {0,0,0,0};
#pragma unroll
        for (int cin = 0; cin < 3; cin++) {
#pragma unroll
            for (int j = 0; j < PROWS; j++) {
                const u64* rowp = tb + (cin * PROWS + j) * RSTRIDE;
                ulonglong2 p0 = *reinterpret_cast<const ulonglong2*>(rowp + oo0);
                ulonglong2 p1 = *reinterpret_cast<const ulonglong2*>(rowp + oo1);
                ulonglong2 p2 = *reinterpret_cast<const ulonglong2*>(rowp + oo2);
                u64 xr[6] = {p0.x, p0.y, p1.x, p1.y, p2.x, p2.y};
                if (j < 3) {                 // P: kh = j
                    const int wb = (cin * 3 + j) * 3;
#pragma unroll
                    for (int kw = 0; kw < 3; kw++) {
                        const u64 wv = wp[wb + kw];
#pragma unroll
                        for (int ww = 0; ww < 4; ww++)
                            accP[ww] = ffma2(wv, xr[ww + kw], accP[ww]);
                    }
                }
                if (j >= 2) {                // Q: kh = j - 2
                    const int wb = (cin * 3 + (j - 2)) * 3;
#pragma unroll
                    for (int kw = 0; kw < 3; kw++) {
                        const u64 wv = wp[wb + kw];
#pragma unroll
                        for (int ww = 0; ww < 4; ww++)
                            accQ[ww] = ffma2(wv, xr[ww + kw], accQ[ww]);
                    }
                }
            }
        }

        // LIF update + spike/reset for both pair sets
        float p0v[4], p1v[4], q0v[4], q1v[4];
#pragma unroll
        for (int k = 0; k < 4; k++) {
            u64 s  = fmul2(fadd2(sgP[k], accP[k]), C2);   // sg=(sg+I)*(1-tg)
            u64 uu = fadd2(uP[k], s);                     // u = u_last + sg
            float ux, uy, sx, sy;
            unpack2(uu, ux, uy);
            unpack2(s,  sx, sy);
            p0v[k] = (ux >= th) ? 1.0f : 0.0f;
            p1v[k] = (uy >= th) ? 1.0f : 0.0f;
            if (ux >= th) { ux = 0.0f; sx = 0.0f; }
            if (uy >= th) { uy = 0.0f; sy = 0.0f; }
            uP[k]  = pack2(ux, uy);
            sgP[k] = pack2(sx, sy);

            s  = fmul2(fadd2(sgQ[k], accQ[k]), C2);
            uu = fadd2(uQ[k], s);
            unpack2(uu, ux, uy);
            unpack2(s,  sx, sy);
            q0v[k] = (ux >= th) ? 1.0f : 0.0f;
            q1v[k] = (uy >= th) ? 1.0f : 0.0f;
            if (ux >= th) { ux = 0.0f; sx = 0.0f; }
            if (uy >= th) { uy = 0.0f; sy = 0.0f; }
            uQ[k]  = pack2(ux, uy);
            sgQ[k] = pack2(sx, sy);
        }
        float* op = ob + (size_t)t * ostride;
        *reinterpret_cast<float4*>(op)            = make_float4(p0v[0], p0v[1], p0v[2], p0v[3]);
        *reinterpret_cast<float4*>(op + WWID)     = make_float4(p1v[0], p1v[1], p1v[2], p1v[3]);
        *reinterpret_cast<float4*>(op + 2 * WWID) = make_float4(q0v[0], q0v[1], q0v[2], q0v[3]);
        *reinterpret_cast<float4*>(op + 3 * WWID) = make_float4(q1v[0], q1v[1], q1v[2], q1v[3]);
    }
}

extern "C" void kernel_launch(void* const* d_in, const int* in_sizes, int n_in,
                              void* d_out, int out_size) {
    const float* x  = (const float*)d_in[0];   // [16,32,3,32,32]
    const float* w  = (const float*)d_in[1];   // [128,3,3,3]
    const float* nw = (const float*)d_in[2];   // [128]
    const float* nb = (const float*)d_in[3];   // [128]
    const float* th = (const float*)d_in[4];   // [128]
    float* out = (float*)d_out;                // [16,32,128,32,32]

    // opt into >48KB dynamic smem (host-side attribute, not a stream op)
    cudaFuncSetAttribute(snn_kernel,
                         cudaFuncAttributeMaxDynamicSharedMemorySize, SMEM_BYTES);

    prep_kernel<<<1, 128>>>(w, nw, nb);
    snn_kernel<<<1024, 256, SMEM_BYTES>>>(x, th, out);
}

// round 17
// speedup vs baseline: 1.7501x; 1.4840x over previous
#include <cuda_runtime.h>

// Fixed shapes for CIFAR10Net_86096914416128
#define TT    16
#define NB    32
#define CIN   3
#define HH    32
#define WWID  32
#define COUT  128
#define KW27  27

// x tile (u64 units): per t, 9 DISJOINT pair-rows (cin*3 + pr) x 34 cols
// pr=0 -> rows (r0-1, r0); pr=1 -> (r0+1, r0+2); pr=2 -> (r0+3, r0+4)
#define RSTRIDE 38                   // 34 + 2x2 gaps -> 304B rows, 16B aligned
#define TSTRIDE (9 * RSTRIDE)        // 342 u64 per t
#define NPAIRS_T (9 * 34)            // 306 pairs per t

typedef unsigned long long u64;

__device__ float g_w[COUT * KW27];

// ---------- packed f32x2 helpers ----------
__device__ __forceinline__ u64 pack2(float a, float b) {
    u64 r; asm("mov.b64 %0,{%1,%2};" : "=l"(r) : "f"(a), "f"(b)); return r;
}
__device__ __forceinline__ void unpack2(u64 v, float& a, float& b) {
    asm("mov.b64 {%0,%1},%2;" : "=f"(a), "=f"(b) : "l"(v));
}
__device__ __forceinline__ u64 ffma2(u64 a, u64 b, u64 c) {
    asm("fma.rn.f32x2 %0,%1,%2,%0;" : "+l"(c) : "l"(a), "l"(b)); return c;
}
__device__ __forceinline__ u64 fadd2(u64 a, u64 b) {
    u64 r; asm("add.rn.f32x2 %0,%1,%2;" : "=l"(r) : "l"(a), "l"(b)); return r;
}
__device__ __forceinline__ u64 fmul2(u64 a, u64 b) {
    u64 r; asm("mul.rn.f32x2 %0,%1,%2;" : "=l"(r) : "l"(a), "l"(b)); return r;
}

// conflict-free column map: 16B gap every 16 cols
__device__ __forceinline__ int colmap(int c) { return c + 2 * (c >> 4); }

// ---------- weight prep: clip + fp32 weight-standardization (matches ref) ----------
__global__ void prep_kernel(const float* __restrict__ w,
                            const float* __restrict__ nw,
                            const float* __restrict__ nb) {
    int c = threadIdx.x;
    if (c >= COUT) return;
    float v[KW27];
    float s = 0.0f;
#pragma unroll
    for (int i = 0; i < KW27; i++) {
        float t = w[c * KW27 + i];
        t = fminf(4.0f, fmaxf(-4.0f, t));
        v[i] = t;
        s = __fadd_rn(s, t);
    }
    float mean = __fdiv_rn(s, 27.0f);
    float ss = 0.0f;
#pragma unroll
    for (int i = 0; i < KW27; i++) {
        float d = __fsub_rn(v[i], mean);
        ss = __fadd_rn(ss, __fmul_rn(d, d));
    }
    float var   = __fdiv_rn(ss, 26.0f);
    float denom = __fsqrt_rn(__fadd_rn(var, 1e-5f));
    float nwc = nw[c];
    float nbc = nb[c];
#pragma unroll
    for (int i = 0; i < KW27; i++) {
        float std = __fdiv_rn(__fsub_rn(v[i], mean), denom);
        g_w[c * KW27 + i] = __fadd_rn(__fmul_rn(std, nwc), nbc);
    }
}

// ---------- fused conv3x3 + LIF scan; disjoint vertical pairs ----------
// Grid: 1024 = b(32) * cgroup(4, 32ch) * rowquad(8). Block: 256 = ch(32)*seg(8).
// Thread: 1 channel, 4 rows (pair-accs P=(r0,r0+1), Q=(r0+2,r0+3)), 4 cols.
// kh=0/2 taps: aligned ffma2 on stored pairs A/B/C.
// kh=1 taps: 2 scalar __fmaf_rn into acc halves (A.hi/B.lo and B.hi/C.lo).
__global__ void __launch_bounds__(256, 2)
snn_kernel(const float* __restrict__ x,
           const float* __restrict__ thr,
           float* __restrict__ out) {
    __shared__ __align__(16) u64 xs[TT * TSTRIDE];   // 43776 B

    const int tid = threadIdx.x;
    const int bid = blockIdx.x;
    const int bb  = bid >> 5;          // batch
    const int cg  = (bid >> 3) & 3;    // 32-channel group
    const int rq  = bid & 7;           // row quad
    const int r0  = rq * 4;

    const int cl  = tid >> 3;          // channel in group
    const int seg = tid & 7;
    const int w0  = seg * 4;
    const int c   = cg * 32 + cl;

    const int HW = HH * WWID;

    // ---- stage ALL 16 timesteps: disjoint pairs (single phase) ----
    for (int idx = tid; idx < TT * NPAIRS_T; idx += 256) {
        int t   = idx / NPAIRS_T;
        int rem = idx - t * NPAIRS_T;
        int row = rem / 34;            // cin*3 + pr
        int col = rem - row * 34;
        int cin = row / 3;
        int pr  = row - cin * 3;
        int gw  = col - 1;
        int ra  = r0 - 1 + 2 * pr;     // [-1, 31]
        int rb  = ra + 1;              // [0, 32]
        float va = 0.0f, vb = 0.0f;
        if (gw >= 0 && gw < WWID) {
            const float* p = x + ((size_t)(t * NB + bb) * CIN + cin) * HW + gw;
            if (ra >= 0 && ra < HH) va = p[ra * WWID];
            if (rb < HH)            vb = p[rb * WWID];
        }
        xs[t * TSTRIDE + row * RSTRIDE + colmap(col)] = pack2(va, vb);
    }

    // ---- weights: pairs for kh=0,2; scalars for kh=1 (overlaps staging LDGs) ----
    u64   wpA[18];   // (cin*2 + (kh==2))*3 + kw
    float wsc[9];    // cin*3 + kw  (kh == 1)
#pragma unroll
    for (int cin = 0; cin < 3; cin++) {
#pragma unroll
        for (int kw = 0; kw < 3; kw++) {
            float w0v = g_w[c * KW27 + (cin * 3 + 0) * 3 + kw];
            float w1v = g_w[c * KW27 + (cin * 3 + 1) * 3 + kw];
            float w2v = g_w[c * KW27 + (cin * 3 + 2) * 3 + kw];
            wpA[(cin * 2 + 0) * 3 + kw] = pack2(w0v, w0v);
            wpA[(cin * 2 + 1) * 3 + kw] = pack2(w2v, w2v);
            wsc[cin * 3 + kw] = w1v;
        }
    }
    const float th = thr[c];
    const float CSG = 1.0f - (float)(1.0 / 3.5);
    const u64 C2 = pack2(CSG, CSG);

    // LIF state: P = rows (r0, r0+1), Q = rows (r0+2, r0+3); 4 cols each
    u64 uP[4]  = {0,0,0,0}, sgP[4] = {0,0,0,0};
    u64 uQ[4]  = {0,0,0,0}, sgQ[4] = {0,0,0,0};

    const int oo0 = colmap(w0);
    const int oo1 = colmap(w0 + 2);
    const int oo2 = colmap(w0 + 4);

    float* ob = out + ((size_t)bb * COUT + c) * HW + (size_t)r0 * WWID + w0;
    const size_t ostride = (size_t)NB * COUT * HW;

    __syncthreads();   // the only barrier

#pragma unroll 1
    for (int t = 0; t < TT; t++) {
        const u64* tb = xs + t * TSTRIDE;

        u64 accP[4] = {0,0,0,0};
        u64 accQ[4] = {0,0,0,0};
#pragma unroll
        for (int cin = 0; cin < 3; cin++) {
            const u64* rA = tb + (cin * 3 + 0) * RSTRIDE;
            const u64* rB = tb + (cin * 3 + 1) * RSTRIDE;
            const u64* rC = tb + (cin * 3 + 2) * RSTRIDE;

            // load A, B
            ulonglong2 a0 = *reinterpret_cast<const ulonglong2*>(rA + oo0);
            ulonglong2 a1 = *reinterpret_cast<const ulonglong2*>(rA + oo1);
            ulonglong2 a2 = *reinterpret_cast<const ulonglong2*>(rA + oo2);
            u64 xa[6] = {a0.x, a0.y, a1.x, a1.y, a2.x, a2.y};
            ulonglong2 b0 = *reinterpret_cast<const ulonglong2*>(rB + oo0);
            ulonglong2 b1 = *reinterpret_cast<const ulonglong2*>(rB + oo1);
            ulonglong2 b2 = *reinterpret_cast<const ulonglong2*>(rB + oo2);
            u64 xb[6] = {b0.x, b0.y, b1.x, b1.y, b2.x, b2.y};

            // ---- P: kh0 aligned on A ----
#pragma unroll
            for (int kw = 0; kw < 3; kw++) {
                const u64 wv = wpA[(cin * 2 + 0) * 3 + kw];
#pragma unroll
                for (int ww = 0; ww < 4; ww++)
                    accP[ww] = ffma2(wv, xa[ww + kw], accP[ww]);
            }
            // ---- P: kh1 scalar on (A.hi, B.lo) ----
#pragma unroll
            for (int kw = 0; kw < 3; kw++) {
                const float ws = wsc[cin * 3 + kw];
#pragma unroll
                for (int ww = 0; ww < 4; ww++) {
                    float alo, ahi, blo, bhi, plo, phi;
                    unpack2(xa[ww + kw], alo, ahi);
                    unpack2(xb[ww + kw], blo, bhi);
                    unpack2(accP[ww], plo, phi);
                    plo = __fmaf_rn(ws, ahi, plo);
                    phi = __fmaf_rn(ws, blo, phi);
                    accP[ww] = pack2(plo, phi);
                }
            }
            // ---- P: kh2 aligned on B ----
#pragma unroll
            for (int kw = 0; kw < 3; kw++) {
                const u64 wv = wpA[(cin * 2 + 1) * 3 + kw];
#pragma unroll
                for (int ww = 0; ww < 4; ww++)
                    accP[ww] = ffma2(wv, xb[ww + kw], accP[ww]);
            }

            // load C (A dead now)
            ulonglong2 c0 = *reinterpret_cast<const ulonglong2*>(rC + oo0);
            ulonglong2 c1 = *reinterpret_cast<const ulonglong2*>(rC + oo1);
            ulonglong2 c2 = *reinterpret_cast<const ulonglong2*>(rC + oo2);
            u64 xc[6] = {c0.x, c0.y, c1.x, c1.y, c2.x, c2.y};

            // ---- Q: kh0 aligned on B ----
#pragma unroll
            for (int kw = 0; kw < 3; kw++) {
                const u64 wv = wpA[(cin * 2 + 0) * 3 + kw];
#pragma unroll
                for (int ww = 0; ww < 4; ww++)
                    accQ[ww] = ffma2(wv, xb[ww + kw], accQ[ww]);
            }
            // ---- Q: kh1 scalar on (B.hi, C.lo) ----
#pragma unroll
            for (int kw = 0; kw < 3; kw++) {
                const float ws = wsc[cin * 3 + kw];
#pragma unroll
                for (int ww = 0; ww < 4; ww++) {
                    float blo, bhi, clo, chi, qlo, qhi;
                    unpack2(xb[ww + kw], blo, bhi);
                    unpack2(xc[ww + kw], clo, chi);
                    unpack2(accQ[ww], qlo, qhi);
                    qlo = __fmaf_rn(ws, bhi, qlo);
                    qhi = __fmaf_rn(ws, clo, qhi);
                    accQ[ww] = pack2(qlo, qhi);
                }
            }
            // ---- Q: kh2 aligned on C ----
#pragma unroll
            for (int kw = 0; kw < 3; kw++) {
                const u64 wv = wpA[(cin * 2 + 1) * 3 + kw];
#pragma unroll
                for (int ww = 0; ww < 4; ww++)
                    accQ[ww] = ffma2(wv, xc[ww + kw], accQ[ww]);
            }
        }

        // LIF update + spike/reset for both pair sets
        float p0v[4], p1v[4], q0v[4], q1v[4];
#pragma unroll
        for (int k = 0; k < 4; k++) {
            u64 s  = fmul2(fadd2(sgP[k], accP[k]), C2);   // sg=(sg+I)*(1-tg)
            u64 uu = fadd2(uP[k], s);                     // u = u_last + sg
            float ux, uy, sx, sy;
            unpack2(uu, ux, uy);
            unpack2(s,  sx, sy);
            p0v[k] = (ux >= th) ? 1.0f : 0.0f;
            p1v[k] = (uy >= th) ? 1.0f : 0.0f;
            if (ux >= th) { ux = 0.0f; sx = 0.0f; }
            if (uy >= th) { uy = 0.0f; sy = 0.0f; }
            uP[k]  = pack2(ux, uy);
            sgP[k] = pack2(sx, sy);

            s  = fmul2(fadd2(sgQ[k], accQ[k]), C2);
            uu = fadd2(uQ[k], s);
            unpack2(uu, ux, uy);
            unpack2(s,  sx, sy);
            q0v[k] = (ux >= th) ? 1.0f : 0.0f;
            q1v[k] = (uy >= th) ? 1.0f : 0.0f;
            if (ux >= th) { ux = 0.0f; sx = 0.0f; }
            if (uy >= th) { uy = 0.0f; sy = 0.0f; }
            uQ[k]  = pack2(ux, uy);
            sgQ[k] = pack2(sx, sy);
        }
        float* op = ob + (size_t)t * ostride;
        *reinterpret_cast<float4*>(op)            = make_float4(p0v[0], p0v[1], p0v[2], p0v[3]);
        *reinterpret_cast<float4*>(op + WWID)     = make_float4(p1v[0], p1v[1], p1v[2], p1v[3]);
        *reinterpret_cast<float4*>(op + 2 * WWID) = make_float4(q0v[0], q0v[1], q0v[2], q0v[3]);
        *reinterpret_cast<float4*>(op + 3 * WWID) = make_float4(q1v[0], q1v[1], q1v[2], q1v[3]);
    }
}

extern "C" void kernel_launch(void* const* d_in, const int* in_sizes, int n_in,
                              void* d_out, int out_size) {
    const float* x  = (const float*)d_in[0];   // [16,32,3,32,32]
    const float* w  = (const float*)d_in[1];   // [128,3,3,3]
    const float* nw = (const float*)d_in[2];   // [128]
    const float* nb = (const float*)d_in[3];   // [128]
    const float* th = (const float*)d_in[4];   // [128]
    float* out = (float*)d_out;                // [16,32,128,32,32]

    prep_kernel<<<1, 128>>>(w, nw, nb);
    snn_kernel<<<1024, 256>>>(x, th, out);
}